// round 16
// baseline (speedup 1.0000x reference)
#include <cuda_runtime.h>
#include <cuda_fp16.h>
#include <cstdint>
#include <cstddef>

// ---------------- problem constants ----------------
#define DIMD   2048
#define MTOT   16384            // 4*4096 tokens
#define N1     6144             // 3*DIMD
#define KD     2048
#define SEQ    4096

// ---------------- scratch ----------------
// GEMM operands in fp16 with 64-wide k-permutation (see v14/v15).
__device__ __half g_xn[(size_t)MTOT * KD];
__device__ __half g_h [(size_t)MTOT * N1];
__device__ __half g_o [(size_t)MTOT * KD];
__device__ __half g_We[(size_t)N1  * KD];
__device__ __half g_Wp[(size_t)KD  * KD];

// ---------------- helpers ----------------
__device__ __forceinline__ uint32_t pk(float a, float b) {
    __half2 h = __floats2half2_rn(a, b);
    return *reinterpret_cast<uint32_t*>(&h);
}
__device__ __forceinline__ void cpasync16(void* smem, const void* gmem) {
    uint32_t s = (uint32_t)__cvta_generic_to_shared(smem);
    asm volatile("cp.async.cg.shared.global [%0], [%1], 16;" :: "r"(s), "l"(gmem));
}
#define CP_COMMIT() asm volatile("cp.async.commit_group;")
#define CP_WAIT1()  asm volatile("cp.async.wait_group 1;")

__device__ __forceinline__ uint4 lds128(uint32_t a) {
    uint4 v;
    asm volatile("ld.shared.v4.b32 {%0,%1,%2,%3}, [%4];"
                 : "=r"(v.x), "=r"(v.y), "=r"(v.z), "=r"(v.w) : "r"(a));
    return v;
}

__device__ __forceinline__ void mma_f16(float c[4], uint32_t a0, uint32_t a1,
                                        uint32_t a2, uint32_t a3,
                                        uint32_t b0, uint32_t b1) {
    asm volatile(
        "mma.sync.aligned.m16n8k16.row.col.f32.f16.f16.f32 "
        "{%0,%1,%2,%3}, {%4,%5,%6,%7}, {%8,%9}, {%0,%1,%2,%3};"
        : "+f"(c[0]), "+f"(c[1]), "+f"(c[2]), "+f"(c[3])
        : "r"(a0), "r"(a1), "r"(a2), "r"(a3), "r"(b0), "r"(b1));
}

// ---------------- fp16 GEMM v16: C[M,N] = A[M,K] * B[N,K]^T ---------------
// CTA 128x128 (2 CTAs/SM!), 8 warps (2Mx4N), warp tile 64x32, BK=64 fp16,
// NSTG=3 (96KB/CTA). 128-reg cap via __launch_bounds__(256,2): acc 64 +
// frags 48. The co-resident CTA hides barrier/LDS latency, so the inner
// loop is a simple load->mma per super-step. Same conflict-free XOR
// swizzle key(row)=((row&1)<<2)|((row>>1)&3), same 64-wide k-perm.
constexpr int BM = 128, BN = 128, NSTG = 3;
constexpr int BKH = 64;                              // halves per k-tile
constexpr int ROW_H = 64;                            // halves per smem row (128B)
constexpr int A_HALVES = BM * ROW_H;                 // 8192
constexpr int B_HALVES = BN * ROW_H;                 // 8192
constexpr int STG_HALVES = A_HALVES + B_HALVES;      // 16384
constexpr int STG_BYTES  = STG_HALVES * 2;           // 32768
constexpr int SMEM_SZ = NSTG * STG_BYTES;            // 98304 B

template<int N, bool HOUT>
__global__ void __launch_bounds__(256, 2) gemm_k(const __half* __restrict__ A,
                                                 const __half* __restrict__ B,
                                                 void* __restrict__ Cout,
                                                 const float* __restrict__ xres,
                                                 const float* __restrict__ cs) {
    constexpr int K = KD;
    constexpr int KT = K / BKH;   // 32
    extern __shared__ __half smem[];
    const uint32_t sbase = (uint32_t)__cvta_generic_to_shared(smem);

    const int bm = blockIdx.y * BM;
    const int bn = blockIdx.x * BN;
    const int tid  = threadIdx.x;
    const int warp = tid >> 5, lane = tid & 31;
    const int wm = (warp & 1) * 64;
    const int wn = (warp >> 1) * 32;
    const int gid = lane >> 2, tig = lane & 3;

    float acc[4][4][4];
    #pragma unroll
    for (int mi = 0; mi < 4; mi++)
        #pragma unroll
        for (int ni = 0; ni < 4; ni++)
            #pragma unroll
            for (int r = 0; r < 4; r++) acc[mi][ni][r] = 0.f;

    const __half* Abase = A + (size_t)bm * K;
    const __half* Bbase = B + (size_t)bn * K;

    auto load_stage = [&](int kt) {
        __half* sa = smem + (kt % NSTG) * STG_HALVES;
        __half* sb = sa + A_HALVES;
        const __half* Ag = Abase + kt * BKH;
        const __half* Bg = Bbase + kt * BKH;
        #pragma unroll
        for (int i = 0; i < 4; i++) {           // A: 1024 chunks, 4/thread
            int c = tid + i * 256;
            int row = c >> 3, ck = c & 7;
            int key = ((row & 1) << 2) | ((row >> 1) & 3);
            cpasync16(sa + row * ROW_H + ((ck ^ key) << 3),
                      Ag + (size_t)row * K + ck * 8);
        }
        #pragma unroll
        for (int i = 0; i < 4; i++) {           // B: 1024 chunks, 4/thread
            int c = tid + i * 256;
            int row = c >> 3, ck = c & 7;
            int key = ((row & 1) << 2) | ((row >> 1) & 3);
            cpasync16(sb + row * ROW_H + ((ck ^ key) << 3),
                      Bg + (size_t)row * K + ck * 8);
        }
    };

    uint4 fa[4][2];   // [mi][row-half]; one super-step (2 k16-steps)
    uint4 fb[4];      // ni 0..3

    const uint32_t key = (uint32_t)(((gid & 1) << 2) | ((gid >> 1) & 3));
    const uint32_t col0 = (uint32_t)((tig ^ key) << 4);
    const uint32_t col1 = (uint32_t)(((4 | tig) ^ key) << 4);
    const uint32_t arow = (uint32_t)(wm + gid) * 128;
    const uint32_t brow = (uint32_t)(A_HALVES * 2) + (uint32_t)(wn + gid) * 128;

    auto super_step = [&](uint32_t aS, uint32_t bS, uint32_t col) {
        #pragma unroll
        for (int mi = 0; mi < 4; mi++) {
            fa[mi][0] = lds128(aS + col + (uint32_t)(mi * 2048));
            fa[mi][1] = lds128(aS + col + (uint32_t)(mi * 2048 + 1024));
        }
        #pragma unroll
        for (int j = 0; j < 4; j++)
            fb[j] = lds128(bS + col + (uint32_t)(j * 1024));
        #pragma unroll
        for (int mi = 0; mi < 4; mi++)
            #pragma unroll
            for (int j = 0; j < 4; j++) {
                mma_f16(acc[mi][j], fa[mi][0].x, fa[mi][1].x,
                                   fa[mi][0].y, fa[mi][1].y, fb[j].x, fb[j].y);
                mma_f16(acc[mi][j], fa[mi][0].z, fa[mi][1].z,
                                   fa[mi][0].w, fa[mi][1].w, fb[j].z, fb[j].w);
            }
    };

    // prologue: 2 stages in flight
    load_stage(0); CP_COMMIT();
    load_stage(1); CP_COMMIT();
    CP_WAIT1();
    __syncthreads();

    #pragma unroll 1
    for (int kt = 0; kt < KT; kt++) {
        const uint32_t stg = sbase + (uint32_t)(kt % NSTG) * STG_BYTES;
        const uint32_t aS = stg + arow;
        const uint32_t bS = stg + brow;

        super_step(aS, bS, col0);
        if (kt + 2 < KT) load_stage(kt + 2);
        CP_COMMIT();
        super_step(aS, bS, col1);

        if (kt + 1 < KT) {
            CP_WAIT1();
            __syncthreads();
        }
    }

    // epilogue
    #pragma unroll
    for (int mi = 0; mi < 4; mi++) {
        #pragma unroll
        for (int ni = 0; ni < 4; ni++) {
            int r0 = bm + wm + mi * 16 + gid;
            int c0 = bn + wn + ni * 8 + tig * 2;
            #pragma unroll
            for (int h = 0; h < 2; h++) {
                int r = r0 + h * 8;
                size_t off = (size_t)r * N + c0;
                float v0 = acc[mi][ni][2 * h + 0];
                float v1 = acc[mi][ni][2 * h + 1];
                if (HOUT) {
                    *(uint32_t*)((__half*)Cout + off) = pk(v0, v1);
                } else {
                    v0 = xres[off]     + cs[c0]     * v0;
                    v1 = xres[off + 1] + cs[c0 + 1] * v1;
                    float2 st; st.x = v0; st.y = v1;
                    *(float2*)((float*)Cout + off) = st;
                }
            }
        }
    }
}

// ---------------- prep: weights -> fp16, 64-wide k-permute ---------------
template<size_t TOTAL>
__global__ void round_perm_k(const float* __restrict__ src, __half* __restrict__ dst) {
    size_t i = (size_t)blockIdx.x * blockDim.x + threadIdx.x;
    if (i >= TOTAL / 32) return;
    const float* s = src + 32 * i;
    float v[32];
    #pragma unroll
    for (int q = 0; q < 8; q++) {
        float4 f = ((const float4*)s)[q];
        v[4*q] = f.x; v[4*q+1] = f.y; v[4*q+2] = f.z; v[4*q+3] = f.w;
    }
    uint4* d4 = (uint4*)(dst + 32 * i);
    #pragma unroll
    for (int t = 0; t < 4; t++) {
        uint4 o;
        o.x = pk(v[2*t],      v[2*t + 1]);
        o.y = pk(v[2*t + 8],  v[2*t + 9]);
        o.z = pk(v[2*t + 16], v[2*t + 17]);
        o.w = pk(v[2*t + 24], v[2*t + 25]);
        d4[t] = o;
    }
}

// ---------------- rmsnorm (emits fp16, 64-perm rows) ---------------------
__global__ void __launch_bounds__(256) rmsnorm_k(const float* __restrict__ x) {
    int row = blockIdx.x;
    const float* xr = x + (size_t)row * DIMD;
    int t = threadIdx.x;
    int g = t >> 3, c = t & 7, sp = (c >> 2) & 1, tt = c & 3;
    int k0 = 64 * g + 32 * sp + 2 * tt;

    float2 p0 = *(const float2*)(xr + k0);
    float2 p1 = *(const float2*)(xr + k0 + 8);
    float2 p2 = *(const float2*)(xr + k0 + 16);
    float2 p3 = *(const float2*)(xr + k0 + 24);
    float ss = p0.x*p0.x + p0.y*p0.y + p1.x*p1.x + p1.y*p1.y
             + p2.x*p2.x + p2.y*p2.y + p3.x*p3.x + p3.y*p3.y;
    #pragma unroll
    for (int off = 16; off > 0; off >>= 1)
        ss += __shfl_xor_sync(0xffffffffu, ss, off);

    __shared__ float red[8];
    __shared__ float sscale;
    int warp = t >> 5, lane = t & 31;
    if (lane == 0) red[warp] = ss;
    __syncthreads();
    if (t == 0) {
        float tot = 0.f;
        #pragma unroll
        for (int i = 0; i < 8; i++) tot += red[i];
        sscale = rsqrtf(tot * (1.0f / DIMD) + 1.1920928955078125e-07f);
    }
    __syncthreads();
    float sc = sscale;

    uint4 st;
    st.x = pk(p0.x * sc, p0.y * sc);
    st.y = pk(p1.x * sc, p1.y * sc);
    st.z = pk(p2.x * sc, p2.y * sc);
    st.w = pk(p3.x * sc, p3.y * sc);
    *(uint4*)(g_xn + (size_t)row * DIMD + 64 * g + 8 * c) = st;
}

// ---------------- gate * causal dwconv * gate (fp16 h in, fp16 perm o out)
__global__ void __launch_bounds__(256) gateconv_k(const float* __restrict__ cw,
                                                  const float* __restrict__ cb,
                                                  const int* __restrict__ dil_p) {
    int dil = *dil_p;
    size_t idx = (size_t)blockIdx.x * blockDim.x + threadIdx.x;
    if (idx >= (size_t)MTOT * 256) return;
    int c = (int)(idx & 255);
    int m = (int)(idx >> 8);
    int s = m % SEQ;
    int g = c >> 3, cc = c & 7, sp = (cc >> 2) & 1, tt = cc & 3;
    int d0 = 64 * g + 32 * sp + 2 * tt;

    const __half* hr  = g_h + (size_t)m * N1;
    const __half* hp1 = hr - (size_t)dil * N1;
    const __half* hp2 = hr - (size_t)(2 * dil) * N1;
    bool ok1 = (s >= dil), ok2 = (s >= 2 * dil);

    uint32_t outw[4];
    #pragma unroll
    for (int p = 0; p < 4; p++) {
        int d = d0 + p * 8;
        float w0a = cw[3*d],   w1a = cw[3*d+1], w2a = cw[3*d+2];
        float w0b = cw[3*d+3], w1b = cw[3*d+4], w2b = cw[3*d+5];
        float2 B0 = __half22float2(*(const __half2*)(hr + d));
        float2 Z0 = __half22float2(*(const __half2*)(hr + 2 * DIMD + d));
        float a0 = cb[d]     + w2a * (B0.x * Z0.x);
        float a1 = cb[d + 1] + w2b * (B0.y * Z0.y);
        if (ok1) {
            float2 B1 = __half22float2(*(const __half2*)(hp1 + d));
            float2 Z1 = __half22float2(*(const __half2*)(hp1 + 2 * DIMD + d));
            a0 += w1a * (B1.x * Z1.x);
            a1 += w1b * (B1.y * Z1.y);
        }
        if (ok2) {
            float2 B2 = __half22float2(*(const __half2*)(hp2 + d));
            float2 Z2 = __half22float2(*(const __half2*)(hp2 + 2 * DIMD + d));
            a0 += w0a * (B2.x * Z2.x);
            a1 += w0b * (B2.y * Z2.y);
        }
        float2 Cg = __half22float2(*(const __half2*)(hr + DIMD + d));
        outw[p] = pk(Cg.x * a0, Cg.y * a1);
    }
    uint4 st; st.x = outw[0]; st.y = outw[1]; st.z = outw[2]; st.w = outw[3];
    *(uint4*)(g_o + (size_t)m * DIMD + 64 * g + 8 * cc) = st;
}

// ---------------- launch ----------------
extern "C" void kernel_launch(void* const* d_in, const int* in_sizes, int n_in,
                              void* d_out, int out_size) {
    const float* x   = (const float*)d_in[0];
    const float* We  = (const float*)d_in[1];
    const float* cw  = (const float*)d_in[2];
    const float* cb  = (const float*)d_in[3];
    const float* Wp  = (const float*)d_in[4];
    const float* cs  = (const float*)d_in[5];
    const int*   dil = (const int*)  d_in[6];
    float* out = (float*)d_out;

    __half *p_xn, *p_h, *p_o, *p_We, *p_Wp;
    cudaGetSymbolAddress((void**)&p_xn, g_xn);
    cudaGetSymbolAddress((void**)&p_h,  g_h);
    cudaGetSymbolAddress((void**)&p_o,  g_o);
    cudaGetSymbolAddress((void**)&p_We, g_We);
    cudaGetSymbolAddress((void**)&p_Wp, g_Wp);

    cudaFuncSetAttribute(gemm_k<N1, true >, cudaFuncAttributeMaxDynamicSharedMemorySize, SMEM_SZ);
    cudaFuncSetAttribute(gemm_k<KD, false>, cudaFuncAttributeMaxDynamicSharedMemorySize, SMEM_SZ);

    {
        constexpr size_t TWE = (size_t)N1 * KD;
        constexpr size_t TWP = (size_t)KD * KD;
        round_perm_k<TWE><<<(unsigned)((TWE / 32 + 255) / 256), 256>>>(We, p_We);
        round_perm_k<TWP><<<(unsigned)((TWP / 32 + 255) / 256), 256>>>(Wp, p_Wp);
    }

    rmsnorm_k<<<MTOT, 256>>>(x);

    // h = xn @ We^T   [16384 x 6144]  (fp16 out)
    gemm_k<N1, true><<<dim3(N1 / BN, MTOT / BM), 256, SMEM_SZ>>>(p_xn, p_We, p_h, nullptr, nullptr);

    {
        size_t n = (size_t)MTOT * 256;
        gateconv_k<<<(unsigned)((n + 255) / 256), 256>>>(cw, cb, dil);
    }

    // out = x + cs * (o @ Wp^T)   [16384 x 2048]  (f32 out, fused residual)
    gemm_k<KD, false><<<dim3(KD / BN, MTOT / BM), 256, SMEM_SZ>>>(p_o, p_Wp, out, x, cs);
}

// round 17
// speedup vs baseline: 1.1393x; 1.1393x over previous
#include <cuda_runtime.h>
#include <cuda_fp16.h>
#include <cstdint>
#include <cstddef>

// ---------------- problem constants ----------------
#define DIMD   2048
#define MTOT   16384            // 4*4096 tokens
#define N1     6144             // 3*DIMD
#define KD     2048
#define SEQ    4096

// ---------------- scratch ----------------
// GEMM operands in fp16 with 64-wide k-permutation (see v14/v15).
__device__ __half g_xn[(size_t)MTOT * KD];
__device__ __half g_h [(size_t)MTOT * N1];
__device__ __half g_o [(size_t)MTOT * KD];
__device__ __half g_We[(size_t)N1  * KD];
__device__ __half g_Wp[(size_t)KD  * KD];

// ---------------- helpers ----------------
__device__ __forceinline__ uint32_t pk(float a, float b) {
    __half2 h = __floats2half2_rn(a, b);
    return *reinterpret_cast<uint32_t*>(&h);
}
__device__ __forceinline__ void cpasync16(void* smem, const void* gmem) {
    uint32_t s = (uint32_t)__cvta_generic_to_shared(smem);
    asm volatile("cp.async.cg.shared.global [%0], [%1], 16;" :: "r"(s), "l"(gmem));
}
#define CP_COMMIT() asm volatile("cp.async.commit_group;")
#define CP_WAIT2()  asm volatile("cp.async.wait_group 2;")

__device__ __forceinline__ uint4 lds128(uint32_t a) {
    uint4 v;
    asm volatile("ld.shared.v4.b32 {%0,%1,%2,%3}, [%4];"
                 : "=r"(v.x), "=r"(v.y), "=r"(v.z), "=r"(v.w) : "r"(a));
    return v;
}

__device__ __forceinline__ void mma_f16(float c[4], uint32_t a0, uint32_t a1,
                                        uint32_t a2, uint32_t a3,
                                        uint32_t b0, uint32_t b1) {
    asm volatile(
        "mma.sync.aligned.m16n8k16.row.col.f32.f16.f16.f32 "
        "{%0,%1,%2,%3}, {%4,%5,%6,%7}, {%8,%9}, {%0,%1,%2,%3};"
        : "+f"(c[0]), "+f"(c[1]), "+f"(c[2]), "+f"(c[3])
        : "r"(a0), "r"(a1), "r"(a2), "r"(a3), "r"(b0), "r"(b1));
}

// ---------------- fp16 GEMM v15 (unchanged — best known) ------------------
constexpr int BM = 128, BN = 256, NSTG = 4;
constexpr int BKH = 64;                              // halves per k-tile
constexpr int ROW_H = 64;                            // halves per smem row (128B)
constexpr int A_HALVES = BM * ROW_H;                 // 8192
constexpr int B_HALVES = BN * ROW_H;                 // 16384
constexpr int STG_HALVES = A_HALVES + B_HALVES;      // 24576
constexpr int STG_BYTES  = STG_HALVES * 2;           // 49152
constexpr int SMEM_SZ = NSTG * STG_BYTES;            // 196608 B

template<int N, bool HOUT>
__global__ void __launch_bounds__(256, 1) gemm_k(const __half* __restrict__ A,
                                                 const __half* __restrict__ B,
                                                 void* __restrict__ Cout,
                                                 const float* __restrict__ xres,
                                                 const float* __restrict__ cs) {
    constexpr int K = KD;
    constexpr int KT = K / BKH;   // 32
    extern __shared__ __half smem[];
    const uint32_t sbase = (uint32_t)__cvta_generic_to_shared(smem);

    const int bm = blockIdx.y * BM;
    const int bn = blockIdx.x * BN;
    const int tid  = threadIdx.x;
    const int warp = tid >> 5, lane = tid & 31;
    const int wm = (warp & 1) * 64;
    const int wn = (warp >> 1) * 64;
    const int gid = lane >> 2, tig = lane & 3;

    float acc[4][8][4];
    #pragma unroll
    for (int mi = 0; mi < 4; mi++)
        #pragma unroll
        for (int ni = 0; ni < 8; ni++)
            #pragma unroll
            for (int r = 0; r < 4; r++) acc[mi][ni][r] = 0.f;

    const __half* Abase = A + (size_t)bm * K;
    const __half* Bbase = B + (size_t)bn * K;

    auto load_stage = [&](int kt) {
        __half* sa = smem + (kt % NSTG) * STG_HALVES;
        __half* sb = sa + A_HALVES;
        const __half* Ag = Abase + kt * BKH;
        const __half* Bg = Bbase + kt * BKH;
        #pragma unroll
        for (int i = 0; i < 4; i++) {           // A: 1024 chunks, 4/thread
            int c = tid + i * 256;
            int row = c >> 3, ck = c & 7;
            int key = ((row & 1) << 2) | ((row >> 1) & 3);
            cpasync16(sa + row * ROW_H + ((ck ^ key) << 3),
                      Ag + (size_t)row * K + ck * 8);
        }
        #pragma unroll
        for (int i = 0; i < 8; i++) {           // B: 2048 chunks, 8/thread
            int c = tid + i * 256;
            int row = c >> 3, ck = c & 7;
            int key = ((row & 1) << 2) | ((row >> 1) & 3);
            cpasync16(sb + row * ROW_H + ((ck ^ key) << 3),
                      Bg + (size_t)row * K + ck * 8);
        }
    };

    uint4 fa[4][2];   // [mi][row-half]; one super-step (2 k16-steps)
    uint4 fb0[4];     // ni 0..3
    uint4 fb1[4];     // ni 4..7

    const uint32_t key = (uint32_t)(((gid & 1) << 2) | ((gid >> 1) & 3));
    const uint32_t col0 = (uint32_t)((tig ^ key) << 4);
    const uint32_t col1 = (uint32_t)(((4 | tig) ^ key) << 4);
    const uint32_t arow = (uint32_t)(wm + gid) * 128;
    const uint32_t brow = (uint32_t)(A_HALVES * 2) + (uint32_t)(wn + gid) * 128;

    auto ldfa = [&](int mi, uint32_t base) {
        fa[mi][0] = lds128(base + (uint32_t)(mi * 2048));
        fa[mi][1] = lds128(base + (uint32_t)(mi * 2048 + 1024));
    };
    auto mma_g = [&](int mi, const uint4* fb, int nib) {
        #pragma unroll
        for (int j = 0; j < 4; j++) {
            int ni = nib + j;
            mma_f16(acc[mi][ni], fa[mi][0].x, fa[mi][1].x,
                                fa[mi][0].y, fa[mi][1].y, fb[j].x, fb[j].y);
            mma_f16(acc[mi][ni], fa[mi][0].z, fa[mi][1].z,
                                fa[mi][0].w, fa[mi][1].w, fb[j].z, fb[j].w);
        }
    };

    load_stage(0); CP_COMMIT();
    load_stage(1); CP_COMMIT();
    load_stage(2); CP_COMMIT();
    CP_WAIT2();
    __syncthreads();
    {
        const uint32_t aB = sbase + arow + col0;
        const uint32_t bB = sbase + brow + col0;
        #pragma unroll
        for (int mi = 0; mi < 4; mi++) ldfa(mi, aB);
        #pragma unroll
        for (int j = 0; j < 4; j++) fb0[j] = lds128(bB + (uint32_t)(j * 1024));
    }

    #pragma unroll 1
    for (int kt = 0; kt < KT; kt++) {
        const uint32_t stg = sbase + (uint32_t)(kt % NSTG) * STG_BYTES;
        const uint32_t aS = stg + arow;
        const uint32_t bS = stg + brow;

        #pragma unroll
        for (int mi = 0; mi < 4; mi++) {
            fb1[mi] = lds128(bS + col0 + (uint32_t)((4 + mi) * 1024));
            mma_g(mi, fb0, 0);
        }
        if (kt + 3 < KT) load_stage(kt + 3);
        CP_COMMIT();
        #pragma unroll
        for (int mi = 0; mi < 4; mi++) {
            mma_g(mi, fb1, 4);
            ldfa(mi, aS + col1);
            fb0[mi] = lds128(bS + col1 + (uint32_t)(mi * 1024));
        }

        #pragma unroll
        for (int mi = 0; mi < 4; mi++) {
            fb1[mi] = lds128(bS + col1 + (uint32_t)((4 + mi) * 1024));
            mma_g(mi, fb0, 0);
        }
        if (kt + 1 < KT) {
            CP_WAIT2();
            __syncthreads();
            const uint32_t nstg = sbase + (uint32_t)((kt + 1) % NSTG) * STG_BYTES;
            const uint32_t naS = nstg + arow + col0;
            const uint32_t nbS = nstg + brow + col0;
            #pragma unroll
            for (int mi = 0; mi < 4; mi++) {
                mma_g(mi, fb1, 4);
                ldfa(mi, naS);
                fb0[mi] = lds128(nbS + (uint32_t)(mi * 1024));
            }
        } else {
            #pragma unroll
            for (int mi = 0; mi < 4; mi++) mma_g(mi, fb1, 4);
        }
    }

    // epilogue
    #pragma unroll
    for (int mi = 0; mi < 4; mi++) {
        #pragma unroll
        for (int ni = 0; ni < 8; ni++) {
            int r0 = bm + wm + mi * 16 + gid;
            int c0 = bn + wn + ni * 8 + tig * 2;
            #pragma unroll
            for (int h = 0; h < 2; h++) {
                int r = r0 + h * 8;
                size_t off = (size_t)r * N + c0;
                float v0 = acc[mi][ni][2 * h + 0];
                float v1 = acc[mi][ni][2 * h + 1];
                if (HOUT) {
                    *(uint32_t*)((__half*)Cout + off) = pk(v0, v1);
                } else {
                    v0 = xres[off]     + cs[c0]     * v0;
                    v1 = xres[off + 1] + cs[c0 + 1] * v1;
                    float2 st; st.x = v0; st.y = v1;
                    *(float2*)((float*)Cout + off) = st;
                }
            }
        }
    }
}

// ---------------- prep: weights -> fp16, 64-wide k-permute ---------------
template<size_t TOTAL>
__global__ void round_perm_k(const float* __restrict__ src, __half* __restrict__ dst) {
    size_t i = (size_t)blockIdx.x * blockDim.x + threadIdx.x;
    if (i >= TOTAL / 32) return;
    const float* s = src + 32 * i;
    float v[32];
    #pragma unroll
    for (int q = 0; q < 8; q++) {
        float4 f = ((const float4*)s)[q];
        v[4*q] = f.x; v[4*q+1] = f.y; v[4*q+2] = f.z; v[4*q+3] = f.w;
    }
    uint4* d4 = (uint4*)(dst + 32 * i);
    #pragma unroll
    for (int t = 0; t < 4; t++) {
        uint4 o;
        o.x = pk(v[2*t],      v[2*t + 1]);
        o.y = pk(v[2*t + 8],  v[2*t + 9]);
        o.z = pk(v[2*t + 16], v[2*t + 17]);
        o.w = pk(v[2*t + 24], v[2*t + 25]);
        d4[t] = o;
    }
}

// ---------------- rmsnorm (emits fp16, 64-perm rows) ---------------------
__global__ void __launch_bounds__(256) rmsnorm_k(const float* __restrict__ x) {
    int row = blockIdx.x;
    const float* xr = x + (size_t)row * DIMD;
    int t = threadIdx.x;
    int g = t >> 3, c = t & 7, sp = (c >> 2) & 1, tt = c & 3;
    int k0 = 64 * g + 32 * sp + 2 * tt;

    float2 p0 = *(const float2*)(xr + k0);
    float2 p1 = *(const float2*)(xr + k0 + 8);
    float2 p2 = *(const float2*)(xr + k0 + 16);
    float2 p3 = *(const float2*)(xr + k0 + 24);
    float ss = p0.x*p0.x + p0.y*p0.y + p1.x*p1.x + p1.y*p1.y
             + p2.x*p2.x + p2.y*p2.y + p3.x*p3.x + p3.y*p3.y;
    #pragma unroll
    for (int off = 16; off > 0; off >>= 1)
        ss += __shfl_xor_sync(0xffffffffu, ss, off);

    __shared__ float red[8];
    __shared__ float sscale;
    int warp = t >> 5, lane = t & 31;
    if (lane == 0) red[warp] = ss;
    __syncthreads();
    if (t == 0) {
        float tot = 0.f;
        #pragma unroll
        for (int i = 0; i < 8; i++) tot += red[i];
        sscale = rsqrtf(tot * (1.0f / DIMD) + 1.1920928955078125e-07f);
    }
    __syncthreads();
    float sc = sscale;

    uint4 st;
    st.x = pk(p0.x * sc, p0.y * sc);
    st.y = pk(p1.x * sc, p1.y * sc);
    st.z = pk(p2.x * sc, p2.y * sc);
    st.w = pk(p3.x * sc, p3.y * sc);
    *(uint4*)(g_xn + (size_t)row * DIMD + 64 * g + 8 * c) = st;
}

// ---------------- gate * causal dwconv * gate — smem-staged, coalesced ---
// One block per token m. Stage h[m] (all 3 slices, 12KB) + B/z slices of
// h[m-dil], h[m-2dil] (4x4KB) into smem with uint4 loads (100% sector
// efficiency), compute from smem, store one 64-perm uint4 per thread.
__global__ void __launch_bounds__(256) gateconv_k(const float* __restrict__ cw,
                                                  const float* __restrict__ cb,
                                                  const int* __restrict__ dil_p) {
    __shared__ __half sh[14336];   // [0:6144) cur | 6144 B1 | 8192 z1 | 10240 B2 | 12288 z2
    int dil = *dil_p;
    int m = blockIdx.x;
    int s = m % SEQ;
    int tid = threadIdx.x;

    const uint4 zero4 = make_uint4(0u, 0u, 0u, 0u);
    bool ok1 = (s >= dil), ok2 = (s >= 2 * dil);

    {
        const uint4* cur = (const uint4*)(g_h + (size_t)m * N1);
        uint4* d = (uint4*)sh;
        #pragma unroll
        for (int i = 0; i < 3; i++) d[tid + 256 * i] = cur[tid + 256 * i];

        const __half* h1 = g_h + (size_t)(m - dil) * N1;
        const __half* h2 = g_h + (size_t)(m - 2 * dil) * N1;
        ((uint4*)(sh + 6144))[tid]  = ok1 ? ((const uint4*)h1)[tid] : zero4;
        ((uint4*)(sh + 8192))[tid]  = ok1 ? ((const uint4*)(h1 + 2 * DIMD))[tid] : zero4;
        ((uint4*)(sh + 10240))[tid] = ok2 ? ((const uint4*)h2)[tid] : zero4;
        ((uint4*)(sh + 12288))[tid] = ok2 ? ((const uint4*)(h2 + 2 * DIMD))[tid] : zero4;
    }
    __syncthreads();

    int g = tid >> 3, cc = tid & 7, sp = (cc >> 2) & 1, tt = cc & 3;
    int d0 = 64 * g + 32 * sp + 2 * tt;

    uint32_t outw[4];
    #pragma unroll
    for (int p = 0; p < 4; p++) {
        int d = d0 + p * 8;
        float w0a = cw[3*d],   w1a = cw[3*d+1], w2a = cw[3*d+2];
        float w0b = cw[3*d+3], w1b = cw[3*d+4], w2b = cw[3*d+5];
        float2 B0 = __half22float2(*(const __half2*)(sh + d));
        float2 Z0 = __half22float2(*(const __half2*)(sh + 2 * DIMD + d));
        float a0 = cb[d]     + w2a * (B0.x * Z0.x);
        float a1 = cb[d + 1] + w2b * (B0.y * Z0.y);
        {
            float2 B1 = __half22float2(*(const __half2*)(sh + 6144 + d));
            float2 Z1 = __half22float2(*(const __half2*)(sh + 8192 + d));
            a0 += w1a * (B1.x * Z1.x);
            a1 += w1b * (B1.y * Z1.y);
        }
        {
            float2 B2 = __half22float2(*(const __half2*)(sh + 10240 + d));
            float2 Z2 = __half22float2(*(const __half2*)(sh + 12288 + d));
            a0 += w0a * (B2.x * Z2.x);
            a1 += w0b * (B2.y * Z2.y);
        }
        float2 Cg = __half22float2(*(const __half2*)(sh + DIMD + d));
        outw[p] = pk(Cg.x * a0, Cg.y * a1);
    }
    uint4 st; st.x = outw[0]; st.y = outw[1]; st.z = outw[2]; st.w = outw[3];
    *(uint4*)(g_o + (size_t)m * DIMD + 64 * g + 8 * cc) = st;
}

// ---------------- launch ----------------
extern "C" void kernel_launch(void* const* d_in, const int* in_sizes, int n_in,
                              void* d_out, int out_size) {
    const float* x   = (const float*)d_in[0];
    const float* We  = (const float*)d_in[1];
    const float* cw  = (const float*)d_in[2];
    const float* cb  = (const float*)d_in[3];
    const float* Wp  = (const float*)d_in[4];
    const float* cs  = (const float*)d_in[5];
    const int*   dil = (const int*)  d_in[6];
    float* out = (float*)d_out;

    __half *p_xn, *p_h, *p_o, *p_We, *p_Wp;
    cudaGetSymbolAddress((void**)&p_xn, g_xn);
    cudaGetSymbolAddress((void**)&p_h,  g_h);
    cudaGetSymbolAddress((void**)&p_o,  g_o);
    cudaGetSymbolAddress((void**)&p_We, g_We);
    cudaGetSymbolAddress((void**)&p_Wp, g_Wp);

    cudaFuncSetAttribute(gemm_k<N1, true >, cudaFuncAttributeMaxDynamicSharedMemorySize, SMEM_SZ);
    cudaFuncSetAttribute(gemm_k<KD, false>, cudaFuncAttributeMaxDynamicSharedMemorySize, SMEM_SZ);

    {
        constexpr size_t TWE = (size_t)N1 * KD;
        constexpr size_t TWP = (size_t)KD * KD;
        round_perm_k<TWE><<<(unsigned)((TWE / 32 + 255) / 256), 256>>>(We, p_We);
        round_perm_k<TWP><<<(unsigned)((TWP / 32 + 255) / 256), 256>>>(Wp, p_Wp);
    }

    rmsnorm_k<<<MTOT, 256>>>(x);

    // h = xn @ We^T   [16384 x 6144]  (fp16 out)
    gemm_k<N1, true><<<dim3(N1 / BN, MTOT / BM), 256, SMEM_SZ>>>(p_xn, p_We, p_h, nullptr, nullptr);

    gateconv_k<<<MTOT, 256>>>(cw, cb, dil);

    // out = x + cs * (o @ Wp^T)   [16384 x 2048]  (f32 out, fused residual)
    gemm_k<KD, false><<<dim3(KD / BN, MTOT / BM), 256, SMEM_SZ>>>(p_o, p_Wp, out, x, cs);
}